// round 7
// baseline (speedup 1.0000x reference)
#include <cuda_runtime.h>
#include <cstdint>

// Motion loss on GB300: 2 threads per (b,t) row (even lane = X skeleton,
// odd lane = Y skeleton), serial quaternion FK per thread, shfl_xor pair
// exchange for loss diffs. NO shared-memory staging: rows are read directly
// from global via __ldg and cached in L1 (each 128B line is re-touched ~8x
// by its owning thread). Zero smem removes the 16-warp/SM occupancy cap ->
// 64 regs, 8 blocks/SM, 32 warps/SM.

namespace {

constexpr int ROW  = 99;                   // floats per row
constexpr int RPB  = 64;                   // rows per block
constexpr int TPB  = 128;                  // 2 threads per row
constexpr int NBT  = 64 * 2048;            // 131072 rows
constexpr int NBLK = NBT / RPB;            // 2048 blocks

// halved loss weights (each lane of a pair accumulates the full joint loss)
constexpr float S1h = 0.5f / (float(NBT) * 96.0f);          // rot mse
constexpr float S2h = 0.5f * 2.5f / (float(NBT) * 72.0f);   // fk  mse * 2.5
constexpr float S3h = 0.5f / (float(NBT) * 3.0f);           // pos mse

} // namespace

__device__ float    g_partials[NBLK];
__device__ unsigned g_count = 0;

struct Xf { float qw, qx, qy, qz, tx, ty, tz; };

__device__ __forceinline__ void qnorm(float& w, float& x, float& y, float& z) {
    float inv = rsqrtf(w*w + x*x + y*y + z*z);
    w *= inv; x *= inv; y *= inv; z *= inv;
}

// child = parent o (local quat l, bone b)
__device__ __forceinline__ void compose(const Xf& p,
                                        float lw, float lx, float ly, float lz,
                                        float bx, float by, float bz, Xf& o) {
    float t2x = 2.f * (p.qy * bz - p.qz * by);
    float t2y = 2.f * (p.qz * bx - p.qx * bz);
    float t2z = 2.f * (p.qx * by - p.qy * bx);
    float ntx = bx + p.qw * t2x + (p.qy * t2z - p.qz * t2y) + p.tx;
    float nty = by + p.qw * t2y + (p.qz * t2x - p.qx * t2z) + p.ty;
    float ntz = bz + p.qw * t2z + (p.qx * t2y - p.qy * t2x) + p.tz;
    float nqw = p.qw * lw - p.qx * lx - p.qy * ly - p.qz * lz;
    float nqx = p.qw * lx + lw * p.qx + (p.qy * lz - p.qz * ly);
    float nqy = p.qw * ly + lw * p.qy + (p.qz * lx - p.qx * lz);
    float nqz = p.qw * lz + lw * p.qz + (p.qx * ly - p.qy * lx);
    o.qw = nqw; o.qx = nqx; o.qy = nqy; o.qz = nqz;
    o.tx = ntx; o.ty = nty; o.tz = ntz;
}

// one non-root joint for ONE skeleton; diffs cross the lane pair via shfl_xor
__device__ __forceinline__ void jstep(const float* __restrict__ r,
                                      const float* __restrict__ bn,
                                      int j,
                                      const Xf& P, Xf& O, float& acc) {
    const unsigned FULL = 0xffffffffu;
    float w = __ldg(r + 4*j + 0), x = __ldg(r + 4*j + 1);
    float y = __ldg(r + 4*j + 2), z = __ldg(r + 4*j + 3);
    qnorm(w, x, y, z);

    float pw = __shfl_xor_sync(FULL, w, 1);
    float px = __shfl_xor_sync(FULL, x, 1);
    float py = __shfl_xor_sync(FULL, y, 1);
    float pz = __shfl_xor_sync(FULL, z, 1);
    float d0 = w - pw, d1 = x - px, d2 = y - py, d3 = z - pz;
    acc += S1h * (d0*d0 + d1*d1 + d2*d2 + d3*d3);

    float bx = __ldg(bn + 3*j + 0), by = __ldg(bn + 3*j + 1), bz = __ldg(bn + 3*j + 2);
    compose(P, w, x, y, z, bx, by, bz, O);

    float ex = O.tx - __shfl_xor_sync(FULL, O.tx, 1);
    float ey = O.ty - __shfl_xor_sync(FULL, O.ty, 1);
    float ez = O.tz - __shfl_xor_sync(FULL, O.tz, 1);
    acc += S2h * (ex*ex + ey*ey + ez*ez);
}

__global__ __launch_bounds__(TPB, 8)
void motion_loss_kernel(const float* __restrict__ Ym,
                        const float* __restrict__ Xm,
                        const float* __restrict__ Yt,
                        const float* __restrict__ Xt,
                        float* __restrict__ out)
{
    const int tid  = threadIdx.x;
    const int bid  = blockIdx.x;
    const int row  = bid * RPB + (tid >> 1);
    const int skel = tid & 1;                // 0 = X, 1 = Y
    const int b    = row >> 11;              // batch item

    const float* r  = (skel ? Ym : Xm) + (size_t)row * ROW;
    const float* bn = (skel ? Yt : Xt) + b * 72;

    const unsigned FULL = 0xffffffffu;
    float acc = 0.f;

    // root: quat 0 + raw position (gtr0 == pos -> pos loss folds in)
    Xf P0;
    {
        float w = __ldg(r + 0), x = __ldg(r + 1), y = __ldg(r + 2), z = __ldg(r + 3);
        qnorm(w, x, y, z);
        float pw = __shfl_xor_sync(FULL, w, 1);
        float px = __shfl_xor_sync(FULL, x, 1);
        float py = __shfl_xor_sync(FULL, y, 1);
        float pz = __shfl_xor_sync(FULL, z, 1);
        float d0 = w - pw, d1 = x - px, d2 = y - py, d3 = z - pz;
        acc += S1h * (d0*d0 + d1*d1 + d2*d2 + d3*d3);

        P0.qw = w; P0.qx = x; P0.qy = y; P0.qz = z;
        P0.tx = __ldg(r + 96); P0.ty = __ldg(r + 97); P0.tz = __ldg(r + 98);
        float ex = P0.tx - __shfl_xor_sync(FULL, P0.tx, 1);
        float ey = P0.ty - __shfl_xor_sync(FULL, P0.ty, 1);
        float ez = P0.tz - __shfl_xor_sync(FULL, P0.tz, 1);
        acc += (S2h + S3h) * (ex*ex + ey*ey + ez*ez);
    }

    Xf A;
    // chain 0 -> 1 -> 4 -> 7 -> 10
    jstep(r, bn,  1, P0, A, acc);
    jstep(r, bn,  4, A,  A, acc);
    jstep(r, bn,  7, A,  A, acc);
    jstep(r, bn, 10, A,  A, acc);
    // chain 0 -> 2 -> 5 -> 8 -> 11
    jstep(r, bn,  2, P0, A, acc);
    jstep(r, bn,  5, A,  A, acc);
    jstep(r, bn,  8, A,  A, acc);
    jstep(r, bn, 11, A,  A, acc);
    // chain 0 -> 3 -> 6 -> 9 (save G9)
    jstep(r, bn,  3, P0, A, acc);
    jstep(r, bn,  6, A,  A, acc);
    jstep(r, bn,  9, A,  A, acc);
    Xf P9 = A;
    // 9 -> 12 -> 15
    jstep(r, bn, 12, P9, A, acc);
    jstep(r, bn, 15, A,  A, acc);
    // 9 -> 13 -> 16 -> 18 -> 20 -> 22
    jstep(r, bn, 13, P9, A, acc);
    jstep(r, bn, 16, A,  A, acc);
    jstep(r, bn, 18, A,  A, acc);
    jstep(r, bn, 20, A,  A, acc);
    jstep(r, bn, 22, A,  A, acc);
    // 9 -> 14 -> 17 -> 19 -> 21 -> 23
    jstep(r, bn, 14, P9, A, acc);
    jstep(r, bn, 17, A,  A, acc);
    jstep(r, bn, 19, A,  A, acc);
    jstep(r, bn, 21, A,  A, acc);
    jstep(r, bn, 23, A,  A, acc);

    // ---- block reduction (4 warps) ----
    #pragma unroll
    for (int o = 16; o > 0; o >>= 1) acc += __shfl_xor_sync(FULL, acc, o);

    __shared__ float wsum[4];
    __shared__ int   s_last;
    const int lane = tid & 31, wid = tid >> 5;
    if (lane == 0) wsum[wid] = acc;
    __syncthreads();

    if (tid == 0) {
        g_partials[bid] = wsum[0] + wsum[1] + wsum[2] + wsum[3];
        __threadfence();
        unsigned ticket = atomicAdd(&g_count, 1u);
        s_last = (ticket == NBLK - 1) ? 1 : 0;
    }
    __syncthreads();

    // ---- last block: deterministic fixed-order final sum ----
    if (s_last) {
        double v = 0.0;
        #pragma unroll
        for (int k = 0; k < NBLK / TPB; ++k)     // 16 per thread
            v += (double)g_partials[tid + k * TPB];

        __shared__ double dsum[TPB];
        dsum[tid] = v;
        __syncthreads();
        #pragma unroll
        for (int o = TPB / 2; o > 0; o >>= 1) {
            if (tid < o) dsum[tid] += dsum[tid + o];
            __syncthreads();
        }
        if (tid == 0) {
            out[0] = (float)dsum[0];
            g_count = 0;                          // reset for next graph replay
        }
    }
}

extern "C" void kernel_launch(void* const* d_in, const int* in_sizes, int n_in,
                              void* d_out, int out_size)
{
    (void)in_sizes; (void)n_in; (void)out_size;
    const float* Ym = (const float*)d_in[0];
    const float* Xm = (const float*)d_in[1];
    const float* Yt = (const float*)d_in[2];
    const float* Xt = (const float*)d_in[3];

    motion_loss_kernel<<<NBLK, TPB>>>(Ym, Xm, Yt, Xt, (float*)d_out);
}

// round 8
// speedup vs baseline: 1.4421x; 1.4421x over previous
#include <cuda_runtime.h>
#include <cstdint>

// Motion loss on GB300: 4 threads per (b,t) row — lane = (row, half, skel).
// Each thread runs HALF of one skeleton's FK chains in a single uniform
// instruction stream (per-lane SELs pick joint index + parent source; no
// divergence). G9 crosses halves via shfl_xor(,2); loss diffs cross skeletons
// via shfl_xor(,1). cp.async staged tiles, 512-thread blocks, 2 blocks/SM
// -> 32 warps/SM at the same smem footprint as the 16-warp R4 kernel.

namespace {

constexpr int ROW   = 99;                  // floats per row
constexpr int RPB   = 128;                 // rows per block
constexpr int TPB   = 512;                 // 4 threads per row
constexpr int NBT   = 64 * 2048;           // 131072 rows
constexpr int NBLK  = NBT / RPB;           // 1024 blocks
constexpr int TILE_F4 = RPB * ROW / 4;     // 3168 float4 per array

constexpr int SY_OFF    = RPB * ROW + 16;  // +16 words: skel pairs 16 banks apart
constexpr int BONES_OFF = SY_OFF + RPB * ROW;
constexpr int SMEM_BYTES = (BONES_OFF + 160) * 4;   // ~102 KB

// joint terms: 2 lanes (skel pair of one half) each add the full term -> 1/2
constexpr float S1h = 0.5f / (float(NBT) * 96.0f);
constexpr float S2h = 0.5f * 2.5f / (float(NBT) * 72.0f);
// root terms: all 4 lanes of a row add them -> 1/4
constexpr float S1q  = 0.25f / (float(NBT) * 96.0f);
constexpr float S2q  = 0.25f * 2.5f / (float(NBT) * 72.0f);
constexpr float S3q  = 0.25f / (float(NBT) * 3.0f);

} // namespace

__device__ float    g_partials[NBLK];
__device__ unsigned g_count = 0;

struct Xf { float qw, qx, qy, qz, tx, ty, tz; };

__device__ __forceinline__ void qnorm(float& w, float& x, float& y, float& z) {
    float inv = rsqrtf(w*w + x*x + y*y + z*z);
    w *= inv; x *= inv; y *= inv; z *= inv;
}

// componentwise select: c ? b : a  (compiles to SELs, no branch)
__device__ __forceinline__ Xf fsel(int c, const Xf& a, const Xf& b) {
    Xf o;
    o.qw = c ? b.qw : a.qw;  o.qx = c ? b.qx : a.qx;
    o.qy = c ? b.qy : a.qy;  o.qz = c ? b.qz : a.qz;
    o.tx = c ? b.tx : a.tx;  o.ty = c ? b.ty : a.ty;  o.tz = c ? b.tz : a.tz;
    return o;
}

// child = parent o (local quat l, bone b)
__device__ __forceinline__ void compose(const Xf& p,
                                        float lw, float lx, float ly, float lz,
                                        float bx, float by, float bz, Xf& o) {
    float t2x = 2.f * (p.qy * bz - p.qz * by);
    float t2y = 2.f * (p.qz * bx - p.qx * bz);
    float t2z = 2.f * (p.qx * by - p.qy * bx);
    float ntx = bx + p.qw * t2x + (p.qy * t2z - p.qz * t2y) + p.tx;
    float nty = by + p.qw * t2y + (p.qz * t2x - p.qx * t2z) + p.ty;
    float ntz = bz + p.qw * t2z + (p.qx * t2y - p.qy * t2x) + p.tz;
    float nqw = p.qw * lw - p.qx * lx - p.qy * ly - p.qz * lz;
    float nqx = p.qw * lx + lw * p.qx + (p.qy * lz - p.qz * ly);
    float nqy = p.qw * ly + lw * p.qy + (p.qz * lx - p.qx * lz);
    float nqz = p.qw * lz + lw * p.qz + (p.qx * ly - p.qy * lx);
    o.qw = nqw; o.qx = nqx; o.qy = nqy; o.qz = nqz;
    o.tx = ntx; o.ty = nty; o.tz = ntz;
}

// one joint step; j is a runtime (per-lane) index; mask covers active lanes
__device__ __forceinline__ void jstep(const float* __restrict__ r,
                                      const float* __restrict__ bn,
                                      int j, unsigned mask,
                                      const Xf& P, Xf& O, float& acc) {
    float w = r[4*j+0], x = r[4*j+1], y = r[4*j+2], z = r[4*j+3];
    qnorm(w, x, y, z);

    float pw = __shfl_xor_sync(mask, w, 1);
    float px = __shfl_xor_sync(mask, x, 1);
    float py = __shfl_xor_sync(mask, y, 1);
    float pz = __shfl_xor_sync(mask, z, 1);
    float d0 = w - pw, d1 = x - px, d2 = y - py, d3 = z - pz;
    acc += S1h * (d0*d0 + d1*d1 + d2*d2 + d3*d3);

    float bx = bn[3*j+0], by = bn[3*j+1], bz = bn[3*j+2];
    compose(P, w, x, y, z, bx, by, bz, O);

    float ex = O.tx - __shfl_xor_sync(mask, O.tx, 1);
    float ey = O.ty - __shfl_xor_sync(mask, O.ty, 1);
    float ez = O.tz - __shfl_xor_sync(mask, O.tz, 1);
    acc += S2h * (ex*ex + ey*ey + ez*ez);
}

__device__ __forceinline__ void cp16(uint32_t dst, const float4* src) {
    asm volatile("cp.async.cg.shared.global [%0], [%1], 16;\n"
                 :: "r"(dst), "l"(src));
}

__global__ __launch_bounds__(TPB, 2)
void motion_loss_kernel(const float* __restrict__ Ym,
                        const float* __restrict__ Xm,
                        const float* __restrict__ Yt,
                        const float* __restrict__ Xt,
                        float* __restrict__ out)
{
    extern __shared__ float sm[];
    const uint32_t smem_base = (uint32_t)__cvta_generic_to_shared(sm);
    const int tid = threadIdx.x;
    const int bid = blockIdx.x;

    // ---- stage 128-row tiles of Xm and Ym (flat float4, coalesced) ----
    {
        const float4* gx = (const float4*)(Xm + (size_t)bid * RPB * ROW);
        const float4* gy = (const float4*)(Ym + (size_t)bid * RPB * ROW);
        const uint32_t dX = smem_base;
        const uint32_t dY = smem_base + (uint32_t)SY_OFF * 4;
        #pragma unroll
        for (int k = 0; k < 7; ++k) {
            int i = tid + k * TPB;
            if (i < TILE_F4) {
                cp16(dX + (uint32_t)i * 16, gx + i);
                cp16(dY + (uint32_t)i * 16, gy + i);
            }
        }
        asm volatile("cp.async.commit_group;\n" ::: "memory");
    }

    // ---- stage bone tables (144 floats) for this block's batch item ----
    const int b = bid >> 4;                 // 16 blocks per batch item
    if (tid < 72)        sm[BONES_OFF + tid] = Xt[b * 72 + tid];
    else if (tid < 144)  sm[BONES_OFF + tid] = Yt[b * 72 + (tid - 72)];

    asm volatile("cp.async.wait_group 0;\n" ::: "memory");
    __syncthreads();

    // lane roles
    const int skel = tid & 1;               // 0 = X, 1 = Y
    const int half = (tid >> 1) & 1;        // chain-set A (0) / B (1)
    const int p    = tid >> 2;              // row within tile
    const float* r  = sm + (skel ? SY_OFF : 0) + p * ROW;
    const float* bn = sm + BONES_OFF + skel * 72;

    const unsigned FULL = 0xffffffffu;
    float acc = 0.f;

    // ---- root (all 4 lanes; quarter weights) ----
    Xf P0;
    {
        float w = r[0], x = r[1], y = r[2], z = r[3];
        qnorm(w, x, y, z);
        float pw = __shfl_xor_sync(FULL, w, 1);
        float px = __shfl_xor_sync(FULL, x, 1);
        float py = __shfl_xor_sync(FULL, y, 1);
        float pz = __shfl_xor_sync(FULL, z, 1);
        float d0 = w - pw, d1 = x - px, d2 = y - py, d3 = z - pz;
        acc += S1q * (d0*d0 + d1*d1 + d2*d2 + d3*d3);

        P0.qw = w; P0.qx = x; P0.qy = y; P0.qz = z;
        P0.tx = r[96]; P0.ty = r[97]; P0.tz = r[98];
        float ex = P0.tx - __shfl_xor_sync(FULL, P0.tx, 1);
        float ey = P0.ty - __shfl_xor_sync(FULL, P0.ty, 1);
        float ez = P0.tz - __shfl_xor_sync(FULL, P0.tz, 1);
        acc += (S2q + S3q) * (ex*ex + ey*ey + ez*ez);
    }

    // ---- 12-step uniform schedule ----
    // half A: 3,6,9 | 1,4,7,10 | 13,16,18,20,22
    // half B: 2,5,8,11 | 12,15 | 14,17,19,21,23
    Xf A, P;
    int j;

    j = half ? 2 : 3;   jstep(r, bn, j, FULL, P0, A, acc);          // s0
    j = half ? 5 : 6;   jstep(r, bn, j, FULL, A,  A, acc);          // s1
    j = half ? 8 : 9;   jstep(r, bn, j, FULL, A,  A, acc);          // s2

    // exchange G9: half-A lanes hold it in A; B receives via shfl_xor(,2)
    Xf P9;
    {
        float sw = __shfl_xor_sync(FULL, A.qw, 2);
        float sx = __shfl_xor_sync(FULL, A.qx, 2);
        float sy = __shfl_xor_sync(FULL, A.qy, 2);
        float sz = __shfl_xor_sync(FULL, A.qz, 2);
        float stx = __shfl_xor_sync(FULL, A.tx, 2);
        float sty = __shfl_xor_sync(FULL, A.ty, 2);
        float stz = __shfl_xor_sync(FULL, A.tz, 2);
        P9.qw = half ? sw : A.qw;  P9.qx = half ? sx : A.qx;
        P9.qy = half ? sy : A.qy;  P9.qz = half ? sz : A.qz;
        P9.tx = half ? stx : A.tx; P9.ty = half ? sty : A.ty;
        P9.tz = half ? stz : A.tz;
    }

    j = half ? 11 : 1;  P = fsel(half, P0, A);
    jstep(r, bn, j, FULL, P, A, acc);                               // s3
    j = half ? 12 : 4;  P = fsel(half, A, P9);
    jstep(r, bn, j, FULL, P, A, acc);                               // s4
    j = half ? 15 : 7;  jstep(r, bn, j, FULL, A, A, acc);           // s5
    j = half ? 14 : 10; P = fsel(half, A, P9);
    jstep(r, bn, j, FULL, P, A, acc);                               // s6
    j = half ? 17 : 13; P = fsel(half, P9, A);
    jstep(r, bn, j, FULL, P, A, acc);                               // s7
    j = half ? 19 : 16; jstep(r, bn, j, FULL, A, A, acc);           // s8
    j = half ? 21 : 18; jstep(r, bn, j, FULL, A, A, acc);           // s9
    j = half ? 23 : 20; jstep(r, bn, j, FULL, A, A, acc);           // s10
    if (!half)          jstep(r, bn, 22, 0x33333333u, A, A, acc);   // s11 (A only)

    // ---- block reduction (16 warps) ----
    #pragma unroll
    for (int o = 16; o > 0; o >>= 1) acc += __shfl_xor_sync(FULL, acc, o);

    __shared__ float wsum[16];
    __shared__ int   s_last;
    const int lane = tid & 31, wid = tid >> 5;
    if (lane == 0) wsum[wid] = acc;
    __syncthreads();

    if (tid == 0) {
        float s = 0.f;
        #pragma unroll
        for (int i = 0; i < 16; ++i) s += wsum[i];
        g_partials[bid] = s;
        __threadfence();
        unsigned ticket = atomicAdd(&g_count, 1u);
        s_last = (ticket == NBLK - 1) ? 1 : 0;
    }
    __syncthreads();

    // ---- last block: deterministic fixed-order final sum ----
    if (s_last) {
        double v = 0.0;
        #pragma unroll
        for (int k = 0; k < NBLK / TPB; ++k)     // 2 per thread
            v += (double)g_partials[tid + k * TPB];

        __shared__ double dsum[TPB];
        dsum[tid] = v;
        __syncthreads();
        #pragma unroll
        for (int o = TPB / 2; o > 0; o >>= 1) {
            if (tid < o) dsum[tid] += dsum[tid + o];
            __syncthreads();
        }
        if (tid == 0) {
            out[0] = (float)dsum[0];
            g_count = 0;                          // reset for next graph replay
        }
    }
}

extern "C" void kernel_launch(void* const* d_in, const int* in_sizes, int n_in,
                              void* d_out, int out_size)
{
    (void)in_sizes; (void)n_in; (void)out_size;
    const float* Ym = (const float*)d_in[0];
    const float* Xm = (const float*)d_in[1];
    const float* Yt = (const float*)d_in[2];
    const float* Xt = (const float*)d_in[3];

    cudaFuncSetAttribute(motion_loss_kernel,
                         cudaFuncAttributeMaxDynamicSharedMemorySize, SMEM_BYTES);
    motion_loss_kernel<<<NBLK, TPB, SMEM_BYTES>>>(Ym, Xm, Yt, Xt, (float*)d_out);
}

// round 9
// speedup vs baseline: 1.6074x; 1.1146x over previous
#include <cuda_runtime.h>
#include <cstdint>

// Motion loss on GB300: thread-per-(b,t)-row with BOTH skeletons packed into
// f32x2 (FFMA2) lanes. X/Y are a perfect 2-wide SIMD dimension: one packed
// fma does the op for both skeletons. No shuffles at all in the FK (loss
// diffs = register-pair unpack + scalar sub/fma). Interleaved smem staging
// ((x,y) float2 pairs -> conflict-free LDS.64), packed bone table, fused
// deterministic reduction.

namespace {

constexpr int ROW   = 99;                  // floats per row (per array)
constexpr int RPB   = 128;                 // rows per block = threads per block
constexpr int TPB   = 128;
constexpr int NBT   = 64 * 2048;           // 131072 rows
constexpr int NBLK  = NBT / RPB;           // 1024 blocks
constexpr int TILE_F4 = RPB * ROW / 4;     // 3168 float4 per array per tile

constexpr int PAIRS      = RPB * ROW;      // 12672 float2 pairs
constexpr int BONES_OFF  = PAIRS;          // in float2 units
constexpr int SMEM_BYTES = (PAIRS + 80) * 8;   // ~102 KB

// full weights: one thread per row adds each term exactly once
constexpr float S1 = 1.0f / (float(NBT) * 96.0f);
constexpr float S2 = 2.5f / (float(NBT) * 72.0f);
constexpr float S3 = 1.0f / (float(NBT) * 3.0f);

} // namespace

__device__ float    g_partials[NBLK];
__device__ unsigned g_count = 0;

using u32 = unsigned int;
using u64 = unsigned long long;

// ---- packed f32x2 primitives ----
__device__ __forceinline__ u64 pk2(float lo, float hi) {
    u64 r;
    asm("mov.b64 %0, {%1, %2};" : "=l"(r)
        : "r"(__float_as_uint(lo)), "r"(__float_as_uint(hi)));
    return r;
}
__device__ __forceinline__ void upk2(u64 v, float& lo, float& hi) {
    u32 a, b;
    asm("mov.b64 {%0, %1}, %2;" : "=r"(a), "=r"(b) : "l"(v));
    lo = __uint_as_float(a); hi = __uint_as_float(b);
}
__device__ __forceinline__ u64 fm2(u64 a, u64 b, u64 c) {
    u64 r; asm("fma.rn.f32x2 %0, %1, %2, %3;" : "=l"(r) : "l"(a), "l"(b), "l"(c));
    return r;
}
__device__ __forceinline__ u64 ml2(u64 a, u64 b) {
    u64 r; asm("mul.rn.f32x2 %0, %1, %2;" : "=l"(r) : "l"(a), "l"(b));
    return r;
}
__device__ __forceinline__ u64 ad2(u64 a, u64 b) {
    u64 r; asm("add.rn.f32x2 %0, %1, %2;" : "=l"(r) : "l"(a), "l"(b));
    return r;
}

constexpr u64 NEG1 = 0xBF800000BF800000ULL;   // (-1, -1)
constexpr u64 TWO  = 0x4000000040000000ULL;   // ( 2,  2)

// packed transform: (quat, translation) for both skeletons
struct PXf { u64 qw, qx, qy, qz, tx, ty, tz; };

// (hi-lo)^2 accumulate into s
__device__ __forceinline__ void d2(u64 v, float& s) {
    float a, b; upk2(v, a, b);
    float d = a - b;
    s = fmaf(d, d, s);
}

// child = parent o (local quat l, bone b); all packed
__device__ __forceinline__ void pcompose(const PXf& p,
                                         u64 lw, u64 lx, u64 ly, u64 lz,
                                         u64 bx, u64 by, u64 bz, PXf& o) {
    u64 nx = ml2(p.qx, NEG1), ny = ml2(p.qy, NEG1), nz = ml2(p.qz, NEG1);
    // c = u x b
    u64 cx = fm2(p.qy, bz, ml2(nz, by));
    u64 cy = fm2(p.qz, bx, ml2(nx, bz));
    u64 cz = fm2(p.qx, by, ml2(ny, bx));
    // s = w*c + u x c
    u64 sx = fm2(p.qw, cx, fm2(p.qy, cz, ml2(nz, cy)));
    u64 sy = fm2(p.qw, cy, fm2(p.qz, cx, ml2(nx, cz)));
    u64 sz = fm2(p.qw, cz, fm2(p.qx, cy, ml2(ny, cx)));
    // t = b + 2s + p.t
    o.tx = fm2(TWO, sx, ad2(bx, p.tx));
    o.ty = fm2(TWO, sy, ad2(by, p.ty));
    o.tz = fm2(TWO, sz, ad2(bz, p.tz));
    // q = p.q * l (Hamilton)
    u64 rw = fm2(p.qw, lw, fm2(nx, lx, fm2(ny, ly, ml2(nz, lz))));
    u64 rx = fm2(p.qw, lx, fm2(lw, p.qx, fm2(p.qy, lz, ml2(nz, ly))));
    u64 ry = fm2(p.qw, ly, fm2(lw, p.qy, fm2(p.qz, lx, ml2(nx, lz))));
    u64 rz = fm2(p.qw, lz, fm2(lw, p.qz, fm2(p.qx, ly, ml2(ny, lx))));
    o.qw = rw; o.qx = rx; o.qy = ry; o.qz = rz;
}

// one non-root joint (both skeletons): normalize + rot loss + compose + fk loss
__device__ __forceinline__ void jstep(const u64* __restrict__ r,
                                      const u64* __restrict__ bn,
                                      int j, const PXf& P, PXf& O, float& acc) {
    u64 w = r[4*j+0], x = r[4*j+1], y = r[4*j+2], z = r[4*j+3];

    u64 n2 = ml2(w, w); n2 = fm2(x, x, n2); n2 = fm2(y, y, n2); n2 = fm2(z, z, n2);
    float na, nb; upk2(n2, na, nb);
    u64 inv = pk2(rsqrtf(na), rsqrtf(nb));
    w = ml2(w, inv); x = ml2(x, inv); y = ml2(y, inv); z = ml2(z, inv);

    float s = 0.f;
    d2(w, s); d2(x, s); d2(y, s); d2(z, s);
    acc = fmaf(S1, s, acc);

    pcompose(P, w, x, y, z, bn[3*j+0], bn[3*j+1], bn[3*j+2], O);

    float t = 0.f;
    d2(O.tx, t); d2(O.ty, t); d2(O.tz, t);
    acc = fmaf(S2, t, acc);
}

__global__ __launch_bounds__(TPB, 2)
void motion_loss_kernel(const float* __restrict__ Ym,
                        const float* __restrict__ Xm,
                        const float* __restrict__ Yt,
                        const float* __restrict__ Xt,
                        float* __restrict__ out)
{
    extern __shared__ float sm[];
    const int tid = threadIdx.x;
    const int bid = blockIdx.x;

    // ---- stage interleaved (x,y) pairs: coalesced LDG.128, STS.128 ----
    {
        const float4* gx = (const float4*)(Xm + (size_t)bid * RPB * ROW);
        const float4* gy = (const float4*)(Ym + (size_t)bid * RPB * ROW);
        float4* d = (float4*)sm;              // pair q at byte offset q*8
        #pragma unroll
        for (int k = 0; k < 25; ++k) {
            int i = tid + k * TPB;
            if (i < TILE_F4) {
                float4 a = __ldg(gx + i);
                float4 c = __ldg(gy + i);
                d[2*i + 0] = make_float4(a.x, c.x, a.y, c.y);
                d[2*i + 1] = make_float4(a.z, c.z, a.w, c.w);
            }
        }
    }

    // ---- stage packed bone table (72 float2 pairs) ----
    const int b = bid >> 4;                   // 16 blocks per batch item
    if (tid < 72) {
        float2* bt = (float2*)sm + BONES_OFF;
        bt[tid] = make_float2(Xt[b * 72 + tid], Yt[b * 72 + tid]);
    }
    __syncthreads();

    const u64* r  = (const u64*)sm + (size_t)tid * ROW;  // this thread's row pairs
    const u64* bn = (const u64*)sm + BONES_OFF;

    float acc = 0.f;

    // ---- root: quat 0 + raw position (gtr0 == pos -> pos loss folds in) ----
    PXf P0;
    {
        u64 w = r[0], x = r[1], y = r[2], z = r[3];
        u64 n2 = ml2(w, w); n2 = fm2(x, x, n2); n2 = fm2(y, y, n2); n2 = fm2(z, z, n2);
        float na, nb; upk2(n2, na, nb);
        u64 inv = pk2(rsqrtf(na), rsqrtf(nb));
        w = ml2(w, inv); x = ml2(x, inv); y = ml2(y, inv); z = ml2(z, inv);

        float s = 0.f;
        d2(w, s); d2(x, s); d2(y, s); d2(z, s);
        acc = fmaf(S1, s, acc);

        P0.qw = w; P0.qx = x; P0.qy = y; P0.qz = z;
        P0.tx = r[96]; P0.ty = r[97]; P0.tz = r[98];
        float t = 0.f;
        d2(P0.tx, t); d2(P0.ty, t); d2(P0.tz, t);
        acc = fmaf(S2 + S3, t, acc);
    }

    // ---- FK chains (separate vars so the scheduler can interleave) ----
    PXf C1, C2, C3, C4, C5, C6;
    // 0 -> 1 -> 4 -> 7 -> 10
    jstep(r, bn,  1, P0, C1, acc);
    jstep(r, bn,  4, C1, C1, acc);
    jstep(r, bn,  7, C1, C1, acc);
    jstep(r, bn, 10, C1, C1, acc);
    // 0 -> 2 -> 5 -> 8 -> 11
    jstep(r, bn,  2, P0, C2, acc);
    jstep(r, bn,  5, C2, C2, acc);
    jstep(r, bn,  8, C2, C2, acc);
    jstep(r, bn, 11, C2, C2, acc);
    // 0 -> 3 -> 6 -> 9  (C3 = G9)
    jstep(r, bn,  3, P0, C3, acc);
    jstep(r, bn,  6, C3, C3, acc);
    jstep(r, bn,  9, C3, C3, acc);
    // 9 -> 12 -> 15
    jstep(r, bn, 12, C3, C4, acc);
    jstep(r, bn, 15, C4, C4, acc);
    // 9 -> 13 -> 16 -> 18 -> 20 -> 22
    jstep(r, bn, 13, C3, C5, acc);
    jstep(r, bn, 16, C5, C5, acc);
    jstep(r, bn, 18, C5, C5, acc);
    jstep(r, bn, 20, C5, C5, acc);
    jstep(r, bn, 22, C5, C5, acc);
    // 9 -> 14 -> 17 -> 19 -> 21 -> 23
    jstep(r, bn, 14, C3, C6, acc);
    jstep(r, bn, 17, C6, C6, acc);
    jstep(r, bn, 19, C6, C6, acc);
    jstep(r, bn, 21, C6, C6, acc);
    jstep(r, bn, 23, C6, C6, acc);

    // ---- block reduction (4 warps) ----
    const unsigned FULL = 0xffffffffu;
    #pragma unroll
    for (int o = 16; o > 0; o >>= 1) acc += __shfl_xor_sync(FULL, acc, o);

    __shared__ float wsum[4];
    __shared__ int   s_last;
    const int lane = tid & 31, wid = tid >> 5;
    if (lane == 0) wsum[wid] = acc;
    __syncthreads();

    if (tid == 0) {
        g_partials[bid] = wsum[0] + wsum[1] + wsum[2] + wsum[3];
        __threadfence();
        unsigned ticket = atomicAdd(&g_count, 1u);
        s_last = (ticket == NBLK - 1) ? 1 : 0;
    }
    __syncthreads();

    // ---- last block: deterministic fixed-order final sum ----
    if (s_last) {
        double v = 0.0;
        #pragma unroll
        for (int k = 0; k < NBLK / TPB; ++k)     // 8 per thread
            v += (double)g_partials[tid + k * TPB];

        __shared__ double dsum[TPB];
        dsum[tid] = v;
        __syncthreads();
        #pragma unroll
        for (int o = TPB / 2; o > 0; o >>= 1) {
            if (tid < o) dsum[tid] += dsum[tid + o];
            __syncthreads();
        }
        if (tid == 0) {
            out[0] = (float)dsum[0];
            g_count = 0;                          // reset for next graph replay
        }
    }
}

extern "C" void kernel_launch(void* const* d_in, const int* in_sizes, int n_in,
                              void* d_out, int out_size)
{
    (void)in_sizes; (void)n_in; (void)out_size;
    const float* Ym = (const float*)d_in[0];
    const float* Xm = (const float*)d_in[1];
    const float* Yt = (const float*)d_in[2];
    const float* Xt = (const float*)d_in[3];

    cudaFuncSetAttribute(motion_loss_kernel,
                         cudaFuncAttributeMaxDynamicSharedMemorySize, SMEM_BYTES);
    motion_loss_kernel<<<NBLK, TPB, SMEM_BYTES>>>(Ym, Xm, Yt, Xt, (float*)d_out);
}

// round 10
// speedup vs baseline: 1.6282x; 1.0130x over previous
#include <cuda_runtime.h>
#include <cstdint>

// Motion loss on GB300: 2 threads per (b,t) row; each thread runs HALF of the
// FK chains with BOTH skeletons packed into f32x2 (FFMA2). Combines R8's
// halved instruction stream with R4/R7's 16-warp/SM occupancy. Packed jsteps
// have zero shuffles (loss diffs = register unpack); only the G9 transform
// crosses the lane pair (7 u64 shfl per row). Divergence-free schedule via
// per-lane SEL of joint index + parent source (validated in R7).

namespace {

constexpr int ROW   = 99;                  // floats per row (per array)
constexpr int RPB   = 128;                 // rows per block
constexpr int TPB   = 256;                 // 2 threads per row
constexpr int NBT   = 64 * 2048;           // 131072 rows
constexpr int NBLK  = NBT / RPB;           // 1024 blocks
constexpr int TILE_F4 = RPB * ROW / 4;     // 3168 float4 per array per tile

constexpr int PAIRS      = RPB * ROW;      // 12672 float2 pairs
constexpr int BONES_OFF  = PAIRS;          // in float2 units
constexpr int SMEM_BYTES = (PAIRS + 80) * 8;   // ~102 KB

// joint terms: exactly one lane of the pair owns each non-root joint -> full
constexpr float S1 = 1.0f / (float(NBT) * 96.0f);
constexpr float S2 = 2.5f / (float(NBT) * 72.0f);
// root terms: both lanes of the pair compute them -> halved
constexpr float S1h  = 0.5f * S1;
constexpr float S23h = 0.5f * (S2 + 1.0f / (float(NBT) * 3.0f));

} // namespace

__device__ float    g_partials[NBLK];
__device__ unsigned g_count = 0;

using u32 = unsigned int;
using u64 = unsigned long long;

// ---- packed f32x2 primitives ----
__device__ __forceinline__ u64 pk2(float lo, float hi) {
    u64 r;
    asm("mov.b64 %0, {%1, %2};" : "=l"(r)
        : "r"(__float_as_uint(lo)), "r"(__float_as_uint(hi)));
    return r;
}
__device__ __forceinline__ void upk2(u64 v, float& lo, float& hi) {
    u32 a, b;
    asm("mov.b64 {%0, %1}, %2;" : "=r"(a), "=r"(b) : "l"(v));
    lo = __uint_as_float(a); hi = __uint_as_float(b);
}
__device__ __forceinline__ u64 fm2(u64 a, u64 b, u64 c) {
    u64 r; asm("fma.rn.f32x2 %0, %1, %2, %3;" : "=l"(r) : "l"(a), "l"(b), "l"(c));
    return r;
}
__device__ __forceinline__ u64 ml2(u64 a, u64 b) {
    u64 r; asm("mul.rn.f32x2 %0, %1, %2;" : "=l"(r) : "l"(a), "l"(b));
    return r;
}
__device__ __forceinline__ u64 ad2(u64 a, u64 b) {
    u64 r; asm("add.rn.f32x2 %0, %1, %2;" : "=l"(r) : "l"(a), "l"(b));
    return r;
}

constexpr u64 NEG1 = 0xBF800000BF800000ULL;   // (-1, -1)
constexpr u64 TWO  = 0x4000000040000000ULL;   // ( 2,  2)

// packed transform: (quat, translation) for both skeletons
struct PXf { u64 qw, qx, qy, qz, tx, ty, tz; };

__device__ __forceinline__ u64 sel64(int c, u64 a, u64 b) { return c ? b : a; }
__device__ __forceinline__ PXf psel(int c, const PXf& a, const PXf& b) {
    PXf o;
    o.qw = sel64(c, a.qw, b.qw); o.qx = sel64(c, a.qx, b.qx);
    o.qy = sel64(c, a.qy, b.qy); o.qz = sel64(c, a.qz, b.qz);
    o.tx = sel64(c, a.tx, b.tx); o.ty = sel64(c, a.ty, b.ty);
    o.tz = sel64(c, a.tz, b.tz);
    return o;
}

// (hi-lo)^2 accumulate into s
__device__ __forceinline__ void d2(u64 v, float& s) {
    float a, b; upk2(v, a, b);
    float d = a - b;
    s = fmaf(d, d, s);
}

// child = parent o (local quat l, bone b); all packed
__device__ __forceinline__ void pcompose(const PXf& p,
                                         u64 lw, u64 lx, u64 ly, u64 lz,
                                         u64 bx, u64 by, u64 bz, PXf& o) {
    u64 nx = ml2(p.qx, NEG1), ny = ml2(p.qy, NEG1), nz = ml2(p.qz, NEG1);
    u64 cx = fm2(p.qy, bz, ml2(nz, by));
    u64 cy = fm2(p.qz, bx, ml2(nx, bz));
    u64 cz = fm2(p.qx, by, ml2(ny, bx));
    u64 sx = fm2(p.qw, cx, fm2(p.qy, cz, ml2(nz, cy)));
    u64 sy = fm2(p.qw, cy, fm2(p.qz, cx, ml2(nx, cz)));
    u64 sz = fm2(p.qw, cz, fm2(p.qx, cy, ml2(ny, cx)));
    o.tx = fm2(TWO, sx, ad2(bx, p.tx));
    o.ty = fm2(TWO, sy, ad2(by, p.ty));
    o.tz = fm2(TWO, sz, ad2(bz, p.tz));
    u64 rw = fm2(p.qw, lw, fm2(nx, lx, fm2(ny, ly, ml2(nz, lz))));
    u64 rx = fm2(p.qw, lx, fm2(lw, p.qx, fm2(p.qy, lz, ml2(nz, ly))));
    u64 ry = fm2(p.qw, ly, fm2(lw, p.qy, fm2(p.qz, lx, ml2(nx, lz))));
    u64 rz = fm2(p.qw, lz, fm2(lw, p.qz, fm2(p.qx, ly, ml2(ny, lx))));
    o.qw = rw; o.qx = rx; o.qy = ry; o.qz = rz;
}

// one non-root joint (both skeletons, runtime joint index)
__device__ __forceinline__ void jstep(const u64* __restrict__ r,
                                      const u64* __restrict__ bn,
                                      int j, const PXf& P, PXf& O, float& acc) {
    u64 w = r[4*j+0], x = r[4*j+1], y = r[4*j+2], z = r[4*j+3];

    u64 n2 = ml2(w, w); n2 = fm2(x, x, n2); n2 = fm2(y, y, n2); n2 = fm2(z, z, n2);
    float na, nb; upk2(n2, na, nb);
    u64 inv = pk2(rsqrtf(na), rsqrtf(nb));
    w = ml2(w, inv); x = ml2(x, inv); y = ml2(y, inv); z = ml2(z, inv);

    float s = 0.f;
    d2(w, s); d2(x, s); d2(y, s); d2(z, s);
    acc = fmaf(S1, s, acc);

    pcompose(P, w, x, y, z, bn[3*j+0], bn[3*j+1], bn[3*j+2], O);

    float t = 0.f;
    d2(O.tx, t); d2(O.ty, t); d2(O.tz, t);
    acc = fmaf(S2, t, acc);
}

__global__ __launch_bounds__(TPB, 2)
void motion_loss_kernel(const float* __restrict__ Ym,
                        const float* __restrict__ Xm,
                        const float* __restrict__ Yt,
                        const float* __restrict__ Xt,
                        float* __restrict__ out)
{
    extern __shared__ float sm[];
    const int tid = threadIdx.x;
    const int bid = blockIdx.x;

    // ---- stage interleaved (x,y) pairs: coalesced LDG.128 -> STS.128 ----
    {
        const float4* gx = (const float4*)(Xm + (size_t)bid * RPB * ROW);
        const float4* gy = (const float4*)(Ym + (size_t)bid * RPB * ROW);
        float4* d = (float4*)sm;              // pair q at byte offset q*8
        #pragma unroll
        for (int k = 0; k < 13; ++k) {
            int i = tid + k * TPB;
            if (i < TILE_F4) {
                float4 a = __ldg(gx + i);
                float4 c = __ldg(gy + i);
                d[2*i + 0] = make_float4(a.x, c.x, a.y, c.y);
                d[2*i + 1] = make_float4(a.z, c.z, a.w, c.w);
            }
        }
    }

    // ---- stage packed bone table (72 float2 pairs) ----
    const int b = bid >> 4;                   // 16 blocks per batch item
    if (tid < 72) {
        float2* bt = (float2*)sm + BONES_OFF;
        bt[tid] = make_float2(Xt[b * 72 + tid], Yt[b * 72 + tid]);
    }
    __syncthreads();

    const int half = tid & 1;                 // 0 = chain-set A, 1 = B
    const int p    = tid >> 1;                // row within tile
    const u64* r  = (const u64*)sm + (size_t)p * ROW;
    const u64* bn = (const u64*)sm + BONES_OFF;

    const unsigned FULL = 0xffffffffu;
    float acc = 0.f;

    // ---- root (both lanes of the pair; half weights) ----
    PXf P0;
    {
        u64 w = r[0], x = r[1], y = r[2], z = r[3];
        u64 n2 = ml2(w, w); n2 = fm2(x, x, n2); n2 = fm2(y, y, n2); n2 = fm2(z, z, n2);
        float na, nb; upk2(n2, na, nb);
        u64 inv = pk2(rsqrtf(na), rsqrtf(nb));
        w = ml2(w, inv); x = ml2(x, inv); y = ml2(y, inv); z = ml2(z, inv);

        float s = 0.f;
        d2(w, s); d2(x, s); d2(y, s); d2(z, s);
        acc = fmaf(S1h, s, acc);

        P0.qw = w; P0.qx = x; P0.qy = y; P0.qz = z;
        P0.tx = r[96]; P0.ty = r[97]; P0.tz = r[98];
        float t = 0.f;
        d2(P0.tx, t); d2(P0.ty, t); d2(P0.tz, t);
        acc = fmaf(S23h, t, acc);
    }

    // ---- 12-step uniform schedule (validated in R7) ----
    // half A: 3,6,9 | 1,4,7,10 | 13,16,18,20,22
    // half B: 2,5,8,11 | 12,15 | 14,17,19,21,23
    PXf A, P;
    int j;

    j = half ? 2 : 3;   jstep(r, bn, j, P0, A, acc);          // s0
    j = half ? 5 : 6;   jstep(r, bn, j, A,  A, acc);          // s1
    j = half ? 8 : 9;   jstep(r, bn, j, A,  A, acc);          // s2

    // exchange G9: A lanes hold it; B receives via shfl_xor(,1)
    PXf P9;
    {
        u64 sw  = __shfl_xor_sync(FULL, A.qw, 1);
        u64 sx  = __shfl_xor_sync(FULL, A.qx, 1);
        u64 sy  = __shfl_xor_sync(FULL, A.qy, 1);
        u64 sz  = __shfl_xor_sync(FULL, A.qz, 1);
        u64 stx = __shfl_xor_sync(FULL, A.tx, 1);
        u64 sty = __shfl_xor_sync(FULL, A.ty, 1);
        u64 stz = __shfl_xor_sync(FULL, A.tz, 1);
        P9.qw = sel64(half, A.qw, sw);  P9.qx = sel64(half, A.qx, sx);
        P9.qy = sel64(half, A.qy, sy);  P9.qz = sel64(half, A.qz, sz);
        P9.tx = sel64(half, A.tx, stx); P9.ty = sel64(half, A.ty, sty);
        P9.tz = sel64(half, A.tz, stz);
    }

    j = half ? 11 : 1;  P = psel(half, P0, A);  jstep(r, bn, j, P, A, acc);  // s3
    j = half ? 12 : 4;  P = psel(half, A, P9);  jstep(r, bn, j, P, A, acc);  // s4
    j = half ? 15 : 7;  jstep(r, bn, j, A, A, acc);                          // s5
    j = half ? 14 : 10; P = psel(half, A, P9);  jstep(r, bn, j, P, A, acc);  // s6
    j = half ? 17 : 13; P = psel(half, P9, A);  jstep(r, bn, j, P, A, acc);  // s7
    j = half ? 19 : 16; jstep(r, bn, j, A, A, acc);                          // s8
    j = half ? 21 : 18; jstep(r, bn, j, A, A, acc);                          // s9
    j = half ? 23 : 20; jstep(r, bn, j, A, A, acc);                          // s10
    if (!half)          jstep(r, bn, 22, A, A, acc);                         // s11 (A only)

    // ---- block reduction (8 warps) ----
    #pragma unroll
    for (int o = 16; o > 0; o >>= 1) acc += __shfl_xor_sync(FULL, acc, o);

    __shared__ float wsum[8];
    __shared__ int   s_last;
    const int lane = tid & 31, wid = tid >> 5;
    if (lane == 0) wsum[wid] = acc;
    __syncthreads();

    if (tid == 0) {
        float s = 0.f;
        #pragma unroll
        for (int i = 0; i < 8; ++i) s += wsum[i];
        g_partials[bid] = s;
        __threadfence();
        unsigned ticket = atomicAdd(&g_count, 1u);
        s_last = (ticket == NBLK - 1) ? 1 : 0;
    }
    __syncthreads();

    // ---- last block: deterministic fixed-order final sum ----
    if (s_last) {
        double v = 0.0;
        #pragma unroll
        for (int k = 0; k < NBLK / TPB; ++k)     // 4 per thread
            v += (double)g_partials[tid + k * TPB];

        __shared__ double dsum[TPB];
        dsum[tid] = v;
        __syncthreads();
        #pragma unroll
        for (int o = TPB / 2; o > 0; o >>= 1) {
            if (tid < o) dsum[tid] += dsum[tid + o];
            __syncthreads();
        }
        if (tid == 0) {
            out[0] = (float)dsum[0];
            g_count = 0;                          // reset for next graph replay
        }
    }
}

extern "C" void kernel_launch(void* const* d_in, const int* in_sizes, int n_in,
                              void* d_out, int out_size)
{
    (void)in_sizes; (void)n_in; (void)out_size;
    const float* Ym = (const float*)d_in[0];
    const float* Xm = (const float*)d_in[1];
    const float* Yt = (const float*)d_in[2];
    const float* Xt = (const float*)d_in[3];

    cudaFuncSetAttribute(motion_loss_kernel,
                         cudaFuncAttributeMaxDynamicSharedMemorySize, SMEM_BYTES);
    motion_loss_kernel<<<NBLK, TPB, SMEM_BYTES>>>(Ym, Xm, Yt, Xt, (float*)d_out);
}

// round 11
// speedup vs baseline: 1.6311x; 1.0017x over previous
#include <cuda_runtime.h>
#include <cstdint>

// Motion loss on GB300: warp-specialized FK halves, both skeletons packed in
// f32x2 (FFMA2). Even warps run chain-half A (3-6-9 then {1-4-7-10} and
// {13-16-18-20-22} interleaved), odd warps half B (2-5-8-11 then {12-15} and
// {14-17-19-21-23}) over the SAME 32 rows. All joint indices are compile-time
// constants (no SELs), G9 crosses the warp pair once via smem, and phase-2
// runs two independent chains per thread for 2x ILP on the critical path.

namespace {

constexpr int ROW   = 99;                  // floats per row (per array)
constexpr int RPB   = 128;                 // rows per block
constexpr int TPB   = 256;                 // 2 threads per row (A-warp + B-warp)
constexpr int NBT   = 64 * 2048;           // 131072 rows
constexpr int NBLK  = NBT / RPB;           // 1024 blocks
constexpr int TILE_F4 = RPB * ROW / 4;     // 3168 float4 per array per tile

constexpr int PAIRS     = RPB * ROW;       // 12672 u64 pairs
constexpr int BONES_OFF = PAIRS;           // u64 units
constexpr int G9_OFF    = BONES_OFF + 72;  // u64 units
constexpr int SMEM_BYTES = (G9_OFF + RPB * 7 + 8) * 8;   // ~109.2 KB

// joint terms owned by exactly one thread -> full weight
constexpr float S1 = 1.0f / (float(NBT) * 96.0f);
constexpr float S2 = 2.5f / (float(NBT) * 72.0f);
// root terms computed by both threads of a row -> half weight
constexpr float S1h  = 0.5f * S1;
constexpr float S23h = 0.5f * (S2 + 1.0f / (float(NBT) * 3.0f));

} // namespace

__device__ float    g_partials[NBLK];
__device__ unsigned g_count = 0;

using u32 = unsigned int;
using u64 = unsigned long long;

// ---- packed f32x2 primitives ----
__device__ __forceinline__ u64 pk2(float lo, float hi) {
    u64 r;
    asm("mov.b64 %0, {%1, %2};" : "=l"(r)
        : "r"(__float_as_uint(lo)), "r"(__float_as_uint(hi)));
    return r;
}
__device__ __forceinline__ void upk2(u64 v, float& lo, float& hi) {
    u32 a, b;
    asm("mov.b64 {%0, %1}, %2;" : "=r"(a), "=r"(b) : "l"(v));
    lo = __uint_as_float(a); hi = __uint_as_float(b);
}
__device__ __forceinline__ u64 fm2(u64 a, u64 b, u64 c) {
    u64 r; asm("fma.rn.f32x2 %0, %1, %2, %3;" : "=l"(r) : "l"(a), "l"(b), "l"(c));
    return r;
}
__device__ __forceinline__ u64 ml2(u64 a, u64 b) {
    u64 r; asm("mul.rn.f32x2 %0, %1, %2;" : "=l"(r) : "l"(a), "l"(b));
    return r;
}
__device__ __forceinline__ u64 ad2(u64 a, u64 b) {
    u64 r; asm("add.rn.f32x2 %0, %1, %2;" : "=l"(r) : "l"(a), "l"(b));
    return r;
}

constexpr u64 NEG1 = 0xBF800000BF800000ULL;
constexpr u64 TWO  = 0x4000000040000000ULL;

struct PXf { u64 qw, qx, qy, qz, tx, ty, tz; };

// (hi-lo)^2 accumulate
__device__ __forceinline__ void d2(u64 v, float& s) {
    float a, b; upk2(v, a, b);
    float d = a - b;
    s = fmaf(d, d, s);
}

__device__ __forceinline__ void pcompose(const PXf& p,
                                         u64 lw, u64 lx, u64 ly, u64 lz,
                                         u64 bx, u64 by, u64 bz, PXf& o) {
    u64 nx = ml2(p.qx, NEG1), ny = ml2(p.qy, NEG1), nz = ml2(p.qz, NEG1);
    u64 cx = fm2(p.qy, bz, ml2(nz, by));
    u64 cy = fm2(p.qz, bx, ml2(nx, bz));
    u64 cz = fm2(p.qx, by, ml2(ny, bx));
    u64 sx = fm2(p.qw, cx, fm2(p.qy, cz, ml2(nz, cy)));
    u64 sy = fm2(p.qw, cy, fm2(p.qz, cx, ml2(nx, cz)));
    u64 sz = fm2(p.qw, cz, fm2(p.qx, cy, ml2(ny, cx)));
    o.tx = fm2(TWO, sx, ad2(bx, p.tx));
    o.ty = fm2(TWO, sy, ad2(by, p.ty));
    o.tz = fm2(TWO, sz, ad2(bz, p.tz));
    u64 rw = fm2(p.qw, lw, fm2(nx, lx, fm2(ny, ly, ml2(nz, lz))));
    u64 rx = fm2(p.qw, lx, fm2(lw, p.qx, fm2(p.qy, lz, ml2(nz, ly))));
    u64 ry = fm2(p.qw, ly, fm2(lw, p.qy, fm2(p.qz, lx, ml2(nx, lz))));
    u64 rz = fm2(p.qw, lz, fm2(lw, p.qz, fm2(p.qx, ly, ml2(ny, lx))));
    o.qw = rw; o.qx = rx; o.qy = ry; o.qz = rz;
}

// one non-root joint (both skeletons); j is compile-time constant at call site
__device__ __forceinline__ void jstep(const u64* __restrict__ r,
                                      const u64* __restrict__ bn,
                                      int j, const PXf& P, PXf& O, float& acc) {
    u64 w = r[4*j+0], x = r[4*j+1], y = r[4*j+2], z = r[4*j+3];

    u64 n2 = ml2(w, w); n2 = fm2(x, x, n2); n2 = fm2(y, y, n2); n2 = fm2(z, z, n2);
    float na, nb; upk2(n2, na, nb);
    u64 inv = pk2(rsqrtf(na), rsqrtf(nb));
    w = ml2(w, inv); x = ml2(x, inv); y = ml2(y, inv); z = ml2(z, inv);

    float s = 0.f;
    d2(w, s); d2(x, s); d2(y, s); d2(z, s);
    acc = fmaf(S1, s, acc);

    pcompose(P, w, x, y, z, bn[3*j+0], bn[3*j+1], bn[3*j+2], O);

    float t = 0.f;
    d2(O.tx, t); d2(O.ty, t); d2(O.tz, t);
    acc = fmaf(S2, t, acc);
}

__global__ __launch_bounds__(TPB, 2)
void motion_loss_kernel(const float* __restrict__ Ym,
                        const float* __restrict__ Xm,
                        const float* __restrict__ Yt,
                        const float* __restrict__ Xt,
                        float* __restrict__ out)
{
    extern __shared__ float sm[];
    const int tid = threadIdx.x;
    const int bid = blockIdx.x;

    // ---- stage interleaved (x,y) pairs: coalesced LDG.128 -> STS.128 ----
    {
        const float4* gx = (const float4*)(Xm + (size_t)bid * RPB * ROW);
        const float4* gy = (const float4*)(Ym + (size_t)bid * RPB * ROW);
        float4* d = (float4*)sm;
        #pragma unroll
        for (int k = 0; k < 13; ++k) {
            int i = tid + k * TPB;
            if (i < TILE_F4) {
                float4 a = __ldg(gx + i);
                float4 c = __ldg(gy + i);
                d[2*i + 0] = make_float4(a.x, c.x, a.y, c.y);
                d[2*i + 1] = make_float4(a.z, c.z, a.w, c.w);
            }
        }
    }

    // ---- stage packed bone table (72 u64 pairs) ----
    const int b = bid >> 4;                    // 16 blocks per batch item
    if (tid < 72) {
        float2* bt = (float2*)sm + BONES_OFF;
        bt[tid] = make_float2(Xt[b * 72 + tid], Yt[b * 72 + tid]);
    }
    __syncthreads();

    const int lane = tid & 31;
    const int wid  = tid >> 5;
    const int isB  = wid & 1;                  // even warp = half A, odd = half B
    const int row  = (wid >> 1) * 32 + lane;   // row within tile (0..127)

    const u64* r  = (const u64*)sm + (size_t)row * ROW;
    const u64* bn = (const u64*)sm + BONES_OFF;
    u64* g9s      = (u64*)sm + G9_OFF + (size_t)row * 7;

    const unsigned FULL = 0xffffffffu;
    float acc = 0.f;

    // ---- root (both warps of a pair; half weights) ----
    PXf P0;
    {
        u64 w = r[0], x = r[1], y = r[2], z = r[3];
        u64 n2 = ml2(w, w); n2 = fm2(x, x, n2); n2 = fm2(y, y, n2); n2 = fm2(z, z, n2);
        float na, nb; upk2(n2, na, nb);
        u64 inv = pk2(rsqrtf(na), rsqrtf(nb));
        w = ml2(w, inv); x = ml2(x, inv); y = ml2(y, inv); z = ml2(z, inv);

        float s = 0.f;
        d2(w, s); d2(x, s); d2(y, s); d2(z, s);
        acc = fmaf(S1h, s, acc);

        P0.qw = w; P0.qx = x; P0.qy = y; P0.qz = z;
        P0.tx = r[96]; P0.ty = r[97]; P0.tz = r[98];
        float t = 0.f;
        d2(P0.tx, t); d2(P0.ty, t); d2(P0.tz, t);
        acc = fmaf(S23h, t, acc);
    }

    // ---- phase 1 ----
    PXf G9;                                    // A: chain 0->3->6->9 result
    if (!isB) {
        jstep(r, bn, 3, P0, G9, acc);
        jstep(r, bn, 6, G9, G9, acc);
        jstep(r, bn, 9, G9, G9, acc);
        g9s[0] = G9.qw; g9s[1] = G9.qx; g9s[2] = G9.qy; g9s[3] = G9.qz;
        g9s[4] = G9.tx; g9s[5] = G9.ty; g9s[6] = G9.tz;
    } else {
        PXf C;                                 // B: chain 0->2->5->8->11
        jstep(r, bn,  2, P0, C, acc);
        jstep(r, bn,  5, C,  C, acc);
        jstep(r, bn,  8, C,  C, acc);
        jstep(r, bn, 11, C,  C, acc);
    }
    __syncthreads();                           // publish G9 to the B warps

    // ---- phase 2: two independent chains per thread, interleaved ----
    if (!isB) {
        PXf C1, C2;
        jstep(r, bn,  1, P0, C1, acc);
        jstep(r, bn, 13, G9, C2, acc);
        jstep(r, bn,  4, C1, C1, acc);
        jstep(r, bn, 16, C2, C2, acc);
        jstep(r, bn,  7, C1, C1, acc);
        jstep(r, bn, 18, C2, C2, acc);
        jstep(r, bn, 10, C1, C1, acc);
        jstep(r, bn, 20, C2, C2, acc);
        jstep(r, bn, 22, C2, C2, acc);
    } else {
        PXf P9;
        P9.qw = g9s[0]; P9.qx = g9s[1]; P9.qy = g9s[2]; P9.qz = g9s[3];
        P9.tx = g9s[4]; P9.ty = g9s[5]; P9.tz = g9s[6];
        PXf C1, C2;
        jstep(r, bn, 12, P9, C1, acc);
        jstep(r, bn, 14, P9, C2, acc);
        jstep(r, bn, 15, C1, C1, acc);
        jstep(r, bn, 17, C2, C2, acc);
        jstep(r, bn, 19, C2, C2, acc);
        jstep(r, bn, 21, C2, C2, acc);
        jstep(r, bn, 23, C2, C2, acc);
    }

    // ---- block reduction (8 warps) ----
    #pragma unroll
    for (int o = 16; o > 0; o >>= 1) acc += __shfl_xor_sync(FULL, acc, o);

    __shared__ float wsum[8];
    __shared__ int   s_last;
    if (lane == 0) wsum[wid] = acc;
    __syncthreads();

    if (tid == 0) {
        float s = 0.f;
        #pragma unroll
        for (int i = 0; i < 8; ++i) s += wsum[i];
        g_partials[bid] = s;
        __threadfence();
        unsigned ticket = atomicAdd(&g_count, 1u);
        s_last = (ticket == NBLK - 1) ? 1 : 0;
    }
    __syncthreads();

    // ---- last block: deterministic fixed-order final sum ----
    if (s_last) {
        double v = 0.0;
        #pragma unroll
        for (int k = 0; k < NBLK / TPB; ++k)     // 4 per thread
            v += (double)g_partials[tid + k * TPB];

        __shared__ double dsum[TPB];
        dsum[tid] = v;
        __syncthreads();
        #pragma unroll
        for (int o = TPB / 2; o > 0; o >>= 1) {
            if (tid < o) dsum[tid] += dsum[tid + o];
            __syncthreads();
        }
        if (tid == 0) {
            out[0] = (float)dsum[0];
            g_count = 0;                          // reset for next graph replay
        }
    }
}

extern "C" void kernel_launch(void* const* d_in, const int* in_sizes, int n_in,
                              void* d_out, int out_size)
{
    (void)in_sizes; (void)n_in; (void)out_size;
    const float* Ym = (const float*)d_in[0];
    const float* Xm = (const float*)d_in[1];
    const float* Yt = (const float*)d_in[2];
    const float* Xt = (const float*)d_in[3];

    cudaFuncSetAttribute(motion_loss_kernel,
                         cudaFuncAttributeMaxDynamicSharedMemorySize, SMEM_BYTES);
    motion_loss_kernel<<<NBLK, TPB, SMEM_BYTES>>>(Ym, Xm, Yt, Xt, (float*)d_out);
}

// round 12
// speedup vs baseline: 1.8085x; 1.1088x over previous
#include <cuda_runtime.h>
#include <cstdint>

// Motion loss on GB300: R10's warp-specialized packed-f32x2 FK, at HALVED
// block granularity: 64 rows / 128 threads / ~55 KB smem -> 4 independent
// blocks per SM (same 16 warps/SM). Four blocks at independent load/compute
// phases keep DRAM busy while others compute, breaking the 2-block phase
// lockstep that capped every 101KB-block variant at ~37 us / 36% DRAM.

namespace {

constexpr int ROW   = 99;                  // floats per row (per array)
constexpr int RPB   = 64;                  // rows per block
constexpr int TPB   = 128;                 // 2 threads per row (A-warp + B-warp)
constexpr int NBT   = 64 * 2048;           // 131072 rows
constexpr int NBLK  = NBT / RPB;           // 2048 blocks
constexpr int TILE_F4 = RPB * ROW / 4;     // 1584 float4 per array per tile

constexpr int PAIRS     = RPB * ROW;       // 6336 u64 pairs
constexpr int BONES_OFF = PAIRS;           // u64 units
constexpr int G9_OFF    = BONES_OFF + 72;  // u64 units
constexpr int SMEM_BYTES = (G9_OFF + RPB * 7 + 8) * 8;   // ~54.9 KB

// joint terms owned by exactly one thread -> full weight
constexpr float S1 = 1.0f / (float(NBT) * 96.0f);
constexpr float S2 = 2.5f / (float(NBT) * 72.0f);
// root terms computed by both threads of a row -> half weight
constexpr float S1h  = 0.5f * S1;
constexpr float S23h = 0.5f * (S2 + 1.0f / (float(NBT) * 3.0f));

} // namespace

__device__ float    g_partials[NBLK];
__device__ unsigned g_count = 0;

using u32 = unsigned int;
using u64 = unsigned long long;

// ---- packed f32x2 primitives ----
__device__ __forceinline__ u64 pk2(float lo, float hi) {
    u64 r;
    asm("mov.b64 %0, {%1, %2};" : "=l"(r)
        : "r"(__float_as_uint(lo)), "r"(__float_as_uint(hi)));
    return r;
}
__device__ __forceinline__ void upk2(u64 v, float& lo, float& hi) {
    u32 a, b;
    asm("mov.b64 {%0, %1}, %2;" : "=r"(a), "=r"(b) : "l"(v));
    lo = __uint_as_float(a); hi = __uint_as_float(b);
}
__device__ __forceinline__ u64 fm2(u64 a, u64 b, u64 c) {
    u64 r; asm("fma.rn.f32x2 %0, %1, %2, %3;" : "=l"(r) : "l"(a), "l"(b), "l"(c));
    return r;
}
__device__ __forceinline__ u64 ml2(u64 a, u64 b) {
    u64 r; asm("mul.rn.f32x2 %0, %1, %2;" : "=l"(r) : "l"(a), "l"(b));
    return r;
}
__device__ __forceinline__ u64 ad2(u64 a, u64 b) {
    u64 r; asm("add.rn.f32x2 %0, %1, %2;" : "=l"(r) : "l"(a), "l"(b));
    return r;
}

constexpr u64 NEG1 = 0xBF800000BF800000ULL;
constexpr u64 TWO  = 0x4000000040000000ULL;

struct PXf { u64 qw, qx, qy, qz, tx, ty, tz; };

// (hi-lo)^2 accumulate
__device__ __forceinline__ void d2(u64 v, float& s) {
    float a, b; upk2(v, a, b);
    float d = a - b;
    s = fmaf(d, d, s);
}

__device__ __forceinline__ void pcompose(const PXf& p,
                                         u64 lw, u64 lx, u64 ly, u64 lz,
                                         u64 bx, u64 by, u64 bz, PXf& o) {
    u64 nx = ml2(p.qx, NEG1), ny = ml2(p.qy, NEG1), nz = ml2(p.qz, NEG1);
    u64 cx = fm2(p.qy, bz, ml2(nz, by));
    u64 cy = fm2(p.qz, bx, ml2(nx, bz));
    u64 cz = fm2(p.qx, by, ml2(ny, bx));
    u64 sx = fm2(p.qw, cx, fm2(p.qy, cz, ml2(nz, cy)));
    u64 sy = fm2(p.qw, cy, fm2(p.qz, cx, ml2(nx, cz)));
    u64 sz = fm2(p.qw, cz, fm2(p.qx, cy, ml2(ny, cx)));
    o.tx = fm2(TWO, sx, ad2(bx, p.tx));
    o.ty = fm2(TWO, sy, ad2(by, p.ty));
    o.tz = fm2(TWO, sz, ad2(bz, p.tz));
    u64 rw = fm2(p.qw, lw, fm2(nx, lx, fm2(ny, ly, ml2(nz, lz))));
    u64 rx = fm2(p.qw, lx, fm2(lw, p.qx, fm2(p.qy, lz, ml2(nz, ly))));
    u64 ry = fm2(p.qw, ly, fm2(lw, p.qy, fm2(p.qz, lx, ml2(nx, lz))));
    u64 rz = fm2(p.qw, lz, fm2(lw, p.qz, fm2(p.qx, ly, ml2(ny, lx))));
    o.qw = rw; o.qx = rx; o.qy = ry; o.qz = rz;
}

// one non-root joint (both skeletons); j is compile-time constant at call site
__device__ __forceinline__ void jstep(const u64* __restrict__ r,
                                      const u64* __restrict__ bn,
                                      int j, const PXf& P, PXf& O, float& acc) {
    u64 w = r[4*j+0], x = r[4*j+1], y = r[4*j+2], z = r[4*j+3];

    u64 n2 = ml2(w, w); n2 = fm2(x, x, n2); n2 = fm2(y, y, n2); n2 = fm2(z, z, n2);
    float na, nb; upk2(n2, na, nb);
    u64 inv = pk2(rsqrtf(na), rsqrtf(nb));
    w = ml2(w, inv); x = ml2(x, inv); y = ml2(y, inv); z = ml2(z, inv);

    float s = 0.f;
    d2(w, s); d2(x, s); d2(y, s); d2(z, s);
    acc = fmaf(S1, s, acc);

    pcompose(P, w, x, y, z, bn[3*j+0], bn[3*j+1], bn[3*j+2], O);

    float t = 0.f;
    d2(O.tx, t); d2(O.ty, t); d2(O.tz, t);
    acc = fmaf(S2, t, acc);
}

__global__ __launch_bounds__(TPB, 4)
void motion_loss_kernel(const float* __restrict__ Ym,
                        const float* __restrict__ Xm,
                        const float* __restrict__ Yt,
                        const float* __restrict__ Xt,
                        float* __restrict__ out)
{
    extern __shared__ float sm[];
    const int tid = threadIdx.x;
    const int bid = blockIdx.x;

    // ---- stage interleaved (x,y) pairs: coalesced LDG.128 -> STS.128 ----
    {
        const float4* gx = (const float4*)(Xm + (size_t)bid * RPB * ROW);
        const float4* gy = (const float4*)(Ym + (size_t)bid * RPB * ROW);
        float4* d = (float4*)sm;
        #pragma unroll
        for (int k = 0; k < 13; ++k) {
            int i = tid + k * TPB;
            if (i < TILE_F4) {
                float4 a = __ldg(gx + i);
                float4 c = __ldg(gy + i);
                d[2*i + 0] = make_float4(a.x, c.x, a.y, c.y);
                d[2*i + 1] = make_float4(a.z, c.z, a.w, c.w);
            }
        }
    }

    // ---- stage packed bone table (72 u64 pairs) ----
    const int b = bid >> 5;                    // 32 blocks per batch item
    if (tid < 72) {
        float2* bt = (float2*)sm + BONES_OFF;
        bt[tid] = make_float2(Xt[b * 72 + tid], Yt[b * 72 + tid]);
    }
    __syncthreads();

    const int lane = tid & 31;
    const int wid  = tid >> 5;                 // 0..3
    const int isB  = wid & 1;                  // even warp = half A, odd = half B
    const int row  = (wid >> 1) * 32 + lane;   // row within tile (0..63)

    const u64* r  = (const u64*)sm + (size_t)row * ROW;
    const u64* bn = (const u64*)sm + BONES_OFF;
    u64* g9s      = (u64*)sm + G9_OFF + (size_t)row * 7;

    const unsigned FULL = 0xffffffffu;
    float acc = 0.f;

    // ---- root (both warps of a pair; half weights) ----
    PXf P0;
    {
        u64 w = r[0], x = r[1], y = r[2], z = r[3];
        u64 n2 = ml2(w, w); n2 = fm2(x, x, n2); n2 = fm2(y, y, n2); n2 = fm2(z, z, n2);
        float na, nb; upk2(n2, na, nb);
        u64 inv = pk2(rsqrtf(na), rsqrtf(nb));
        w = ml2(w, inv); x = ml2(x, inv); y = ml2(y, inv); z = ml2(z, inv);

        float s = 0.f;
        d2(w, s); d2(x, s); d2(y, s); d2(z, s);
        acc = fmaf(S1h, s, acc);

        P0.qw = w; P0.qx = x; P0.qy = y; P0.qz = z;
        P0.tx = r[96]; P0.ty = r[97]; P0.tz = r[98];
        float t = 0.f;
        d2(P0.tx, t); d2(P0.ty, t); d2(P0.tz, t);
        acc = fmaf(S23h, t, acc);
    }

    // ---- phase 1 ----
    PXf G9;                                    // A: chain 0->3->6->9 result
    if (!isB) {
        jstep(r, bn, 3, P0, G9, acc);
        jstep(r, bn, 6, G9, G9, acc);
        jstep(r, bn, 9, G9, G9, acc);
        g9s[0] = G9.qw; g9s[1] = G9.qx; g9s[2] = G9.qy; g9s[3] = G9.qz;
        g9s[4] = G9.tx; g9s[5] = G9.ty; g9s[6] = G9.tz;
    } else {
        PXf C;                                 // B: chain 0->2->5->8->11
        jstep(r, bn,  2, P0, C, acc);
        jstep(r, bn,  5, C,  C, acc);
        jstep(r, bn,  8, C,  C, acc);
        jstep(r, bn, 11, C,  C, acc);
    }
    __syncthreads();                           // publish G9 to the B warps

    // ---- phase 2: two independent chains per thread, interleaved ----
    if (!isB) {
        PXf C1, C2;
        jstep(r, bn,  1, P0, C1, acc);
        jstep(r, bn, 13, G9, C2, acc);
        jstep(r, bn,  4, C1, C1, acc);
        jstep(r, bn, 16, C2, C2, acc);
        jstep(r, bn,  7, C1, C1, acc);
        jstep(r, bn, 18, C2, C2, acc);
        jstep(r, bn, 10, C1, C1, acc);
        jstep(r, bn, 20, C2, C2, acc);
        jstep(r, bn, 22, C2, C2, acc);
    } else {
        PXf P9;
        P9.qw = g9s[0]; P9.qx = g9s[1]; P9.qy = g9s[2]; P9.qz = g9s[3];
        P9.tx = g9s[4]; P9.ty = g9s[5]; P9.tz = g9s[6];
        PXf C1, C2;
        jstep(r, bn, 12, P9, C1, acc);
        jstep(r, bn, 14, P9, C2, acc);
        jstep(r, bn, 15, C1, C1, acc);
        jstep(r, bn, 17, C2, C2, acc);
        jstep(r, bn, 19, C2, C2, acc);
        jstep(r, bn, 21, C2, C2, acc);
        jstep(r, bn, 23, C2, C2, acc);
    }

    // ---- block reduction (4 warps) ----
    #pragma unroll
    for (int o = 16; o > 0; o >>= 1) acc += __shfl_xor_sync(FULL, acc, o);

    __shared__ float wsum[4];
    __shared__ int   s_last;
    if (lane == 0) wsum[wid] = acc;
    __syncthreads();

    if (tid == 0) {
        g_partials[bid] = wsum[0] + wsum[1] + wsum[2] + wsum[3];
        __threadfence();
        unsigned ticket = atomicAdd(&g_count, 1u);
        s_last = (ticket == NBLK - 1) ? 1 : 0;
    }
    __syncthreads();

    // ---- last block: deterministic fixed-order final sum ----
    if (s_last) {
        double v = 0.0;
        #pragma unroll
        for (int k = 0; k < NBLK / TPB; ++k)     // 16 per thread
            v += (double)g_partials[tid + k * TPB];

        __shared__ double dsum[TPB];
        dsum[tid] = v;
        __syncthreads();
        #pragma unroll
        for (int o = TPB / 2; o > 0; o >>= 1) {
            if (tid < o) dsum[tid] += dsum[tid + o];
            __syncthreads();
        }
        if (tid == 0) {
            out[0] = (float)dsum[0];
            g_count = 0;                          // reset for next graph replay
        }
    }
}

extern "C" void kernel_launch(void* const* d_in, const int* in_sizes, int n_in,
                              void* d_out, int out_size)
{
    (void)in_sizes; (void)n_in; (void)out_size;
    const float* Ym = (const float*)d_in[0];
    const float* Xm = (const float*)d_in[1];
    const float* Yt = (const float*)d_in[2];
    const float* Xt = (const float*)d_in[3];

    cudaFuncSetAttribute(motion_loss_kernel,
                         cudaFuncAttributeMaxDynamicSharedMemorySize, SMEM_BYTES);
    motion_loss_kernel<<<NBLK, TPB, SMEM_BYTES>>>(Ym, Xm, Yt, Xt, (float*)d_out);
}